// round 13
// baseline (speedup 1.0000x reference)
#include <cuda_runtime.h>
#include <cuda_fp16.h>
#include <math.h>
#include <stdint.h>

typedef unsigned long long u64;
typedef unsigned int u32;

// ---------------- problem constants ----------------
#define BSZ   4096
#define DIM   128
#define KNBR  64
#define NREL  16
#define KAGG  2048          // NREL * DIM
#define KCAT  2176          // KAGG + DIM
#define NQKV  384
#define NSPLIT 8            // split-K for layer GEMMs (34 tiles -> 4..5 each)
#define LAYER_TILES 34      // KCAT / 64

// ---------------- device scratch ----------------
__device__ __half g_aggh[BSZ * KAGG];
__device__ float  g_x   [3][BSZ * DIM];        // fp32 x0,x1 (residuals)
__device__ __half g_xh  [3 * BSZ * DIM];       // x0,x1,x2 hi
__device__ float  g_qkv [2 * BSZ * NQKV];
__device__ __half g_oh  [BSZ * DIM];
__device__ __half g_ol  [BSZ * DIM];
__device__ __half g_Wt  [2 * DIM * KCAT];      // B for layer gemm, [l][e][k], fp16
__device__ __half g_in  [NQKV * DIM];          // in_proj_w fp16
__device__ __half g_out [DIM * DIM];           // out_proj_w fp16
__device__ __half g_part[NSPLIT * BSZ * DIM];  // fp16 split-K partials

// ================= PTX helpers =================
__device__ __forceinline__ u32 smem_u32(const void* p) {
    u32 a; asm("{ .reg .u64 t; cvta.to.shared.u64 t, %1; cvt.u32.u64 %0, t; }" : "=r"(a) : "l"(p));
    return a;
}
__device__ __forceinline__ void cp16(u32 s, const void* g) {
    asm volatile("cp.async.cg.shared.global [%0], [%1], 16;" :: "r"(s), "l"(g));
}
__device__ __forceinline__ void cp_commit() {
    asm volatile("cp.async.commit_group;" ::: "memory");
}
__device__ __forceinline__ void cp_wait0() {
    asm volatile("cp.async.wait_group 0;" ::: "memory");
}
__device__ __forceinline__ void cp_wait1() {
    asm volatile("cp.async.wait_group 1;" ::: "memory");
}
__device__ __forceinline__ void ldsm4(u32* r, u32 addr) {
    asm volatile("ldmatrix.sync.aligned.m8n8.x4.shared.b16 {%0,%1,%2,%3}, [%4];"
                 : "=r"(r[0]), "=r"(r[1]), "=r"(r[2]), "=r"(r[3]) : "r"(addr));
}
__device__ __forceinline__ void mma16816(float* c, const u32* a, const u32* b) {
    asm volatile(
        "mma.sync.aligned.m16n8k16.row.col.f32.f16.f16.f32 "
        "{%0,%1,%2,%3}, {%4,%5,%6,%7}, {%8,%9}, {%0,%1,%2,%3};"
        : "+f"(c[0]), "+f"(c[1]), "+f"(c[2]), "+f"(c[3])
        : "r"(a[0]), "r"(a[1]), "r"(a[2]), "r"(a[3]), "r"(b[0]), "r"(b[1]));
}
__device__ __forceinline__ void split_f16(float v, __half& h, __half& l) {
    h = __float2half_rn(v);
    l = __float2half_rn(v - __half2float(h));
}

// ================= merged prep kernel =================
__global__ void __launch_bounds__(256)
prep_all(const float* __restrict__ Wrel,
         const float* __restrict__ resW,
         const float* __restrict__ inW,
         const float* __restrict__ outW)
{
    const int blk = blockIdx.x;
    if (blk < 512) {
        __shared__ float tile[32][33];
        const int mat = blk >> 4;            // l*16 + r
        const int by  = (blk >> 2) & 3;
        const int bx  = blk & 3;
        const int l = mat >> 4, r = mat & 15;
        const int tx = threadIdx.x & 31, ty = threadIdx.x >> 5;
        const float* src = Wrel + (long)mat * 16384;
        int e_in = bx * 32 + tx;
        #pragma unroll
        for (int i = 0; i < 4; i++) {
            int d = by * 32 + ty + i * 8;
            tile[ty + i * 8][tx] = src[d * 128 + e_in];
        }
        __syncthreads();
        const long base = (long)l * (DIM * KCAT);
        #pragma unroll
        for (int i = 0; i < 4; i++) {
            int e = bx * 32 + ty + i * 8;
            int d = by * 32 + tx;
            g_Wt[base + (long)e * KCAT + r * 128 + d] = __float2half_rn(tile[tx][ty + i * 8]);
        }
    } else {
        int i = (blk - 512) * 256 + threadIdx.x;
        const int NR = 2 * DIM * DIM;
        const int NI = NQKV * DIM;
        const int NO = DIM * DIM;
        if (i < NR) {
            int l = i >> 14, e = (i >> 7) & 127, d = i & 127;
            g_Wt[(long)l * (DIM * KCAT) + (long)e * KCAT + 2048 + d] = __float2half_rn(resW[i]);
        } else if (i < NR + NI) {
            int t = i - NR;
            g_in[t] = __float2half_rn(inW[t]);
        } else if (i < NR + NI + NO) {
            int t = i - NR - NI;
            g_out[t] = __float2half_rn(outW[t]);
        }
    }
}

// ---------------- agg: relation scatter + x0 gather (fp16 hi outputs) ------
__global__ void __launch_bounds__(128)
agg_kernel(const int* __restrict__ drug,
           const int* __restrict__ adjE,
           const int* __restrict__ adjR,
           const float* __restrict__ ew,
           const float* __restrict__ E)
{
    __shared__ float s[NREL * DIM];
    __shared__ int   se[KNBR];
    __shared__ int   sr[KNBR];
    __shared__ float sw[KNBR];

    const int b = blockIdx.x;
    const int d = threadIdx.x;

    #pragma unroll
    for (int r = 0; r < NREL; r++) s[r * DIM + d] = 0.f;

    if (d < KNBR) {
        se[d] = adjE[b * KNBR + d];
        sr[d] = adjR[b * KNBR + d];
        sw[d] = ew  [b * KNBR + d];
    }
    {
        float v = E[(long)drug[b] * DIM + d];
        g_x[0][b * DIM + d] = v;
        g_xh[b * DIM + d] = __float2half_rn(v);
    }
    __syncthreads();

    #pragma unroll 1
    for (int k = 0; k < KNBR; k += 4) {
        float e0 = E[(long)se[k + 0] * DIM + d];
        float e1 = E[(long)se[k + 1] * DIM + d];
        float e2 = E[(long)se[k + 2] * DIM + d];
        float e3 = E[(long)se[k + 3] * DIM + d];
        s[sr[k + 0] * DIM + d] += sw[k + 0] * e0;
        s[sr[k + 1] * DIM + d] += sw[k + 1] * e1;
        s[sr[k + 2] * DIM + d] += sw[k + 2] * e2;
        s[sr[k + 3] * DIM + d] += sw[k + 3] * e3;
    }
    const long ao = (long)b * KAGG;
    #pragma unroll
    for (int r = 0; r < NREL; r++)
        g_aggh[ao + r * DIM + d] = __float2half_rn(s[r * DIM + d]);
}

// ================= fp16 tensor-core GEMM, 64-wide k-tiles ==================
// 256 threads / 8 warps; CTA tile 128x128; warp tile 32x64; 2 CTAs/SM (1-pass).
// C[m,n] = sum_k A[m,k]*B[n,k]; A = [A1 | A2] fp16 (lo limbs iff NPASS==2).
// 3-stage cp.async pipeline, ONE barrier per 64-wide k-tile.
// HALF_OUT: write __half C (split-K partials); else float C (+bias).
#define ROWB   144               // 128B data + 16B pad (stride 36 words)
#define REGB   18432             // 128 * 144

template<int NPASS, bool HALF_OUT>
__global__ void __launch_bounds__(256, 2)
gemm_f16(const __half* __restrict__ A1h, const __half* __restrict__ A1l, int K1,
         const __half* __restrict__ A2h, const __half* __restrict__ A2l, int K2,
         const __half* __restrict__ Bm, int KB,
         void* __restrict__ Cv, int ldC, long partStride,
         int tiles_total, const float* __restrict__ bias)
{
    constexpr u32 STAGE = (NPASS + 1) * REGB;
    constexpr u32 BOFF  = NPASS * REGB;

    extern __shared__ __align__(128) char smem[];
    const u32 sb  = smem_u32(smem);
    const int tid = threadIdx.x, lane = tid & 31, wid = tid >> 5;
    const int bm  = blockIdx.x * 128;
    const int bn  = blockIdx.y * 128;

    const int tb = (tiles_total * blockIdx.z) / gridDim.z;
    const int te = (tiles_total * (blockIdx.z + 1)) / gridDim.z;
    const int ntiles = te - tb;
    const int kbeg = tb * 64;

    // producer mapping: thread -> (row, 64B segment)
    const int prow = tid >> 1, pseg = tid & 1;
    const u32 pdst = (u32)(prow * ROWB + pseg * 64);

    auto issue = [&](int t, int s) {
        const int k0 = kbeg + t * 64;
        const __half *pAh, *pAl = nullptr;
        if (k0 < K1) {
            long o = (long)(bm + prow) * K1 + k0 + pseg * 32;
            pAh = A1h + o; if (NPASS == 2) pAl = A1l + o;
        } else {
            long o = (long)(bm + prow) * K2 + (k0 - K1) + pseg * 32;
            pAh = A2h + o; if (NPASS == 2) pAl = A2l + o;
        }
        long ob = (long)(bn + prow) * KB + k0 + pseg * 32;
        u32 d = sb + s * STAGE + pdst;
        #pragma unroll
        for (int i = 0; i < 4; i++) {
            cp16(d + i * 16, pAh + i * 8);
            if (NPASS == 2) cp16(d + REGB + i * 16, pAl + i * 8);
            cp16(d + BOFF + i * 16, Bm + ob + i * 8);
        }
        cp_commit();
    };

    // consumer mapping: 8 warps -> 4 (m) x 2 (n); warp tile 32x64
    const int wr = wid & 3, wc = wid >> 2;
    const u32 a_off = (u32)((wr * 32 + (lane & 15)) * ROWB + (lane >> 4) * 16);
    const u32 b_off = (u32)(BOFF +
                            (wc * 64 + (lane & 7) + ((lane >> 4) & 1) * 8) * ROWB +
                            ((lane >> 3) & 1) * 16);

    float acc[2][8][4];
    #pragma unroll
    for (int i = 0; i < 2; i++)
        #pragma unroll
        for (int j = 0; j < 8; j++)
            #pragma unroll
            for (int q = 0; q < 4; q++) acc[i][j][q] = 0.f;

    issue(0, 0);
    if (ntiles > 1) issue(1, 1);

    for (int t = 0; t < ntiles; t++) {
        const int s = t % 3;
        if (t + 1 < ntiles) cp_wait1(); else cp_wait0();
        __syncthreads();   // stage s visible; all warps done with stage (t+2)%3
        if (t + 2 < ntiles) issue(t + 2, (t + 2) % 3);

        const u32 base = sb + s * STAGE;
        #pragma unroll
        for (int kk = 0; kk < 64; kk += 16) {
            u32 ah[2][4], bx[4][4];
            #pragma unroll
            for (int mi = 0; mi < 2; mi++)
                ldsm4(ah[mi], base + a_off + mi * (16 * ROWB) + kk * 2);
            #pragma unroll
            for (int nj = 0; nj < 4; nj++)
                ldsm4(bx[nj], base + b_off + nj * (16 * ROWB) + kk * 2);
            #pragma unroll
            for (int mi = 0; mi < 2; mi++)
                #pragma unroll
                for (int nt = 0; nt < 8; nt++)
                    mma16816(acc[mi][nt], ah[mi], &bx[nt >> 1][(nt & 1) * 2]);
            if (NPASS == 2) {
                u32 al[2][4];
                #pragma unroll
                for (int mi = 0; mi < 2; mi++)
                    ldsm4(al[mi], base + REGB + a_off + mi * (16 * ROWB) + kk * 2);
                #pragma unroll
                for (int mi = 0; mi < 2; mi++)
                    #pragma unroll
                    for (int nt = 0; nt < 8; nt++)
                        mma16816(acc[mi][nt], al[mi], &bx[nt >> 1][(nt & 1) * 2]);
            }
        }
    }

    // epilogue
    const int gr  = bm + wr * 32 + (lane >> 2);
    const int gcb = bn + wc * 64 + (lane & 3) * 2;
    if (HALF_OUT) {
        __half* Cp = (__half*)Cv + (long)blockIdx.z * partStride;
        #pragma unroll
        for (int mi = 0; mi < 2; mi++)
            #pragma unroll
            for (int nt = 0; nt < 8; nt++) {
                int r0 = gr + mi * 16;
                int c  = gcb + nt * 8;
                *(__half2*)(Cp + (long)r0 * ldC + c) =
                    __halves2half2(__float2half_rn(acc[mi][nt][0]), __float2half_rn(acc[mi][nt][1]));
                *(__half2*)(Cp + (long)(r0 + 8) * ldC + c) =
                    __halves2half2(__float2half_rn(acc[mi][nt][2]), __float2half_rn(acc[mi][nt][3]));
            }
    } else {
        float* Cp = (float*)Cv + (long)blockIdx.z * partStride;
        #pragma unroll
        for (int mi = 0; mi < 2; mi++)
            #pragma unroll
            for (int nt = 0; nt < 8; nt++) {
                int r0 = gr + mi * 16;
                int c  = gcb + nt * 8;
                float b0 = 0.f, b1 = 0.f;
                if (bias) { b0 = bias[c]; b1 = bias[c + 1]; }
                *(float2*)(Cp + (long)r0 * ldC + c) =
                    make_float2(acc[mi][nt][0] + b0, acc[mi][nt][1] + b1);
                *(float2*)(Cp + (long)(r0 + 8) * ldC + c) =
                    make_float2(acc[mi][nt][2] + b0, acc[mi][nt][3] + b1);
            }
    }
}

// ---------------- split-K combine (fp16 partials) + bias + residual + relu -
__global__ void __launch_bounds__(256)
combine_layer(const float* __restrict__ bias,
              const float* __restrict__ xin,
              float* __restrict__ xout,
              __half* __restrict__ xh)
{
    const int i = blockIdx.x * 256 + threadIdx.x;      // over BSZ*DIM/4
    const __half2* p = (const __half2*)g_part;
    const int Q2 = BSZ * DIM / 2;
    float2 a01 = make_float2(0.f, 0.f), a23 = make_float2(0.f, 0.f);
    #pragma unroll
    for (int q = 0; q < NSPLIT; q++) {
        float2 v0 = __half22float2(p[q * Q2 + 2 * i]);
        float2 v1 = __half22float2(p[q * Q2 + 2 * i + 1]);
        a01.x += v0.x; a01.y += v0.y; a23.x += v1.x; a23.y += v1.y;
    }
    float4 xi = ((const float4*)xin)[i];
    float4 bb = ((const float4*)bias)[i & 31];
    float4 o;
    o.x = fmaxf(a01.x + xi.x + bb.x, 0.f);
    o.y = fmaxf(a01.y + xi.y + bb.y, 0.f);
    o.z = fmaxf(a23.x + xi.z + bb.z, 0.f);
    o.w = fmaxf(a23.y + xi.w + bb.w, 0.f);
    ((float4*)xout)[i] = o;

    __half2* ph = (__half2*)xh;
    ph[2 * i]     = __halves2half2(__float2half_rn(o.x), __float2half_rn(o.y));
    ph[2 * i + 1] = __halves2half2(__float2half_rn(o.z), __float2half_rn(o.w));
}

// ---------------- attention (L=2, one warp per head) ----------------
__global__ void __launch_bounds__(128)
attn_kernel()
{
    const int b = blockIdx.x;
    const int h = threadIdx.x >> 5;
    const int d = threadIdx.x & 31;

    const float* p0 = g_qkv + (long)b * NQKV + h * 32 + d;
    const float* p1 = p0 + (long)BSZ * NQKV;
    float q0 = p0[0], k0 = p0[128], v0 = p0[256];
    float q1 = p1[0], k1 = p1[128], v1 = p1[256];

    float s00 = q0 * k0, s01 = q0 * k1, s10 = q1 * k0, s11 = q1 * k1;
    #pragma unroll
    for (int o = 16; o; o >>= 1) {
        s00 += __shfl_xor_sync(0xffffffffu, s00, o);
        s01 += __shfl_xor_sync(0xffffffffu, s01, o);
        s10 += __shfl_xor_sync(0xffffffffu, s10, o);
        s11 += __shfl_xor_sync(0xffffffffu, s11, o);
    }
    const float inv = 0.17677669529663687f;  // 1/sqrt(32)
    s00 *= inv; s01 *= inv; s10 *= inv; s11 *= inv;

    float m0 = fmaxf(s00, s01), m1 = fmaxf(s10, s11);
    float e00 = expf(s00 - m0), e01 = expf(s01 - m0);
    float e10 = expf(s10 - m1), e11 = expf(s11 - m1);
    float o0 = (e00 * v0 + e01 * v1) / (e00 + e01);
    float o1 = (e10 * v0 + e11 * v1) / (e10 + e11);

    float v = 0.5f * (o0 + o1);
    __half hh, ll; split_f16(v, hh, ll);
    g_oh[(long)b * DIM + h * 32 + d] = hh;
    g_ol[(long)b * DIM + h * 32 + d] = ll;
}

// ---------------- host launcher ----------------
extern "C" void kernel_launch(void* const* d_in, const int* in_sizes, int n_in,
                              void* d_out, int out_size)
{
    const int*   drug = (const int*)  d_in[0];
    const int*   adjE = (const int*)  d_in[1];
    const int*   adjR = (const int*)  d_in[2];
    const float* ew   = (const float*)d_in[3];
    const float* E    = (const float*)d_in[4];
    const float* Wrel = (const float*)d_in[5];
    const float* resW = (const float*)d_in[6];
    const float* resb = (const float*)d_in[7];
    const float* inW  = (const float*)d_in[8];
    const float* inB  = (const float*)d_in[9];
    const float* outW = (const float*)d_in[10];
    const float* outB = (const float*)d_in[11];

    __half *aggh, *xh, *oh, *ol, *Wt, *inw, *outw, *part;
    float *xf, *qkv;
    cudaGetSymbolAddress((void**)&aggh, g_aggh);
    cudaGetSymbolAddress((void**)&xf,   g_x);
    cudaGetSymbolAddress((void**)&xh,   g_xh);
    cudaGetSymbolAddress((void**)&qkv,  g_qkv);
    cudaGetSymbolAddress((void**)&oh,   g_oh);
    cudaGetSymbolAddress((void**)&ol,   g_ol);
    cudaGetSymbolAddress((void**)&Wt,   g_Wt);
    cudaGetSymbolAddress((void**)&inw,  g_in);
    cudaGetSymbolAddress((void**)&outw, g_out);
    cudaGetSymbolAddress((void**)&part, g_part);

    const int SM1 = 3 * 2 * REGB;   // 110592
    const int SM2 = 3 * 3 * REGB;   // 165888 (out-proj: 1 CTA/SM, fine)
    cudaFuncSetAttribute((const void*)gemm_f16<1, true>,
                         cudaFuncAttributeMaxDynamicSharedMemorySize, SM1);
    cudaFuncSetAttribute((const void*)gemm_f16<1, false>,
                         cudaFuncAttributeMaxDynamicSharedMemorySize, SM1);
    cudaFuncSetAttribute((const void*)gemm_f16<2, false>,
                         cudaFuncAttributeMaxDynamicSharedMemorySize, SM2);

    prep_all<<<896, 256>>>(Wrel, resW, inW, outW);
    agg_kernel<<<BSZ, 128>>>(drug, adjE, adjR, ew, E);

    // layer 0 (1-pass, fp16 partials): part = split-K((agg|x0) @ Wcat0^T)
    gemm_f16<1, true><<<dim3(BSZ / 128, 1, NSPLIT), 256, SM1>>>(
        aggh, nullptr, KAGG, xh, nullptr, DIM, Wt, KCAT,
        part, DIM, (long)BSZ * DIM, LAYER_TILES, nullptr);
    combine_layer<<<BSZ * DIM / 4 / 256, 256>>>(
        resb, xf, xf + BSZ * DIM, xh + BSZ * DIM);

    // layer 1 (1-pass, fp16 partials)
    gemm_f16<1, true><<<dim3(BSZ / 128, 1, NSPLIT), 256, SM1>>>(
        aggh, nullptr, KAGG, xh + BSZ * DIM, nullptr, DIM,
        Wt + DIM * KCAT, KCAT,
        part, DIM, (long)BSZ * DIM, LAYER_TILES, nullptr);
    combine_layer<<<BSZ * DIM / 4 / 256, 256>>>(
        resb + DIM, xf + BSZ * DIM, xf + 2 * BSZ * DIM,
        xh + 2 * BSZ * DIM);

    // qkv for both layer outputs (1-pass, fp32 out): M=8192, N=384, K=128
    gemm_f16<1, false><<<dim3(2 * BSZ / 128, NQKV / 128, 1), 256, SM1>>>(
        xh + BSZ * DIM, nullptr, DIM, nullptr, nullptr, 0,
        inw, DIM, qkv, NQKV, 0, 2, inB);

    attn_kernel<<<BSZ, 128>>>();

    // out projection (2-pass, fp32 out): M=4096, N=128, K=128 -> d_out
    gemm_f16<2, false><<<dim3(BSZ / 128, 1, 1), 256, SM2>>>(
        oh, ol, DIM, nullptr, nullptr, 0,
        outw, DIM, d_out, DIM, 0, 2, outB);
}

// round 14
// speedup vs baseline: 1.0660x; 1.0660x over previous
#include <cuda_runtime.h>
#include <cuda_fp16.h>
#include <math.h>
#include <stdint.h>

typedef unsigned long long u64;
typedef unsigned int u32;

// ---------------- problem constants ----------------
#define BSZ   4096
#define DIM   128
#define KNBR  64
#define NREL  16
#define KAGG  2048          // NREL * DIM
#define KCAT  2176          // KAGG + DIM
#define NQKV  384
#define NSPLIT 8            // split-K for layer GEMMs (68 tiles -> 8..9 each)
#define LAYER_TILES 68      // KCAT / 32

// ---------------- device scratch ----------------
__device__ __half g_aggh[BSZ * KAGG];
__device__ float  g_x   [3][BSZ * DIM];        // fp32 x0,x1 (residuals)
__device__ __half g_xh  [3 * BSZ * DIM];       // x0,x1,x2 hi
__device__ float  g_qkv [2 * BSZ * NQKV];
__device__ __half g_oh  [BSZ * DIM];
__device__ __half g_ol  [BSZ * DIM];
__device__ __half g_Wt  [2 * DIM * KCAT];      // B for layer gemm, [l][e][k], fp16
__device__ __half g_in  [NQKV * DIM];          // in_proj_w fp16
__device__ __half g_out [DIM * DIM];           // out_proj_w fp16
__device__ __half g_part[NSPLIT * BSZ * DIM];  // fp16 split-K partials

// ================= PTX helpers =================
__device__ __forceinline__ u32 smem_u32(const void* p) {
    u32 a; asm("{ .reg .u64 t; cvta.to.shared.u64 t, %1; cvt.u32.u64 %0, t; }" : "=r"(a) : "l"(p));
    return a;
}
__device__ __forceinline__ void cp16(u32 s, const void* g) {
    asm volatile("cp.async.cg.shared.global [%0], [%1], 16;" :: "r"(s), "l"(g));
}
__device__ __forceinline__ void cp_commit() {
    asm volatile("cp.async.commit_group;" ::: "memory");
}
__device__ __forceinline__ void cp_wait0() {
    asm volatile("cp.async.wait_group 0;" ::: "memory");
}
__device__ __forceinline__ void cp_wait1() {
    asm volatile("cp.async.wait_group 1;" ::: "memory");
}
__device__ __forceinline__ void ldsm4(u32* r, u32 addr) {
    asm volatile("ldmatrix.sync.aligned.m8n8.x4.shared.b16 {%0,%1,%2,%3}, [%4];"
                 : "=r"(r[0]), "=r"(r[1]), "=r"(r[2]), "=r"(r[3]) : "r"(addr));
}
__device__ __forceinline__ void mma16816(float* c, const u32* a, const u32* b) {
    asm volatile(
        "mma.sync.aligned.m16n8k16.row.col.f32.f16.f16.f32 "
        "{%0,%1,%2,%3}, {%4,%5,%6,%7}, {%8,%9}, {%0,%1,%2,%3};"
        : "+f"(c[0]), "+f"(c[1]), "+f"(c[2]), "+f"(c[3])
        : "r"(a[0]), "r"(a[1]), "r"(a[2]), "r"(a[3]), "r"(b[0]), "r"(b[1]));
}
__device__ __forceinline__ void split_f16(float v, __half& h, __half& l) {
    h = __float2half_rn(v);
    l = __float2half_rn(v - __half2float(h));
}

// ================= merged prep kernel =================
__global__ void __launch_bounds__(256)
prep_all(const float* __restrict__ Wrel,
         const float* __restrict__ resW,
         const float* __restrict__ inW,
         const float* __restrict__ outW)
{
    const int blk = blockIdx.x;
    if (blk < 512) {
        __shared__ float tile[32][33];
        const int mat = blk >> 4;            // l*16 + r
        const int by  = (blk >> 2) & 3;
        const int bx  = blk & 3;
        const int l = mat >> 4, r = mat & 15;
        const int tx = threadIdx.x & 31, ty = threadIdx.x >> 5;
        const float* src = Wrel + (long)mat * 16384;
        int e_in = bx * 32 + tx;
        #pragma unroll
        for (int i = 0; i < 4; i++) {
            int d = by * 32 + ty + i * 8;
            tile[ty + i * 8][tx] = src[d * 128 + e_in];
        }
        __syncthreads();
        const long base = (long)l * (DIM * KCAT);
        #pragma unroll
        for (int i = 0; i < 4; i++) {
            int e = bx * 32 + ty + i * 8;
            int d = by * 32 + tx;
            g_Wt[base + (long)e * KCAT + r * 128 + d] = __float2half_rn(tile[tx][ty + i * 8]);
        }
    } else {
        int i = (blk - 512) * 256 + threadIdx.x;
        const int NR = 2 * DIM * DIM;
        const int NI = NQKV * DIM;
        const int NO = DIM * DIM;
        if (i < NR) {
            int l = i >> 14, e = (i >> 7) & 127, d = i & 127;
            g_Wt[(long)l * (DIM * KCAT) + (long)e * KCAT + 2048 + d] = __float2half_rn(resW[i]);
        } else if (i < NR + NI) {
            int t = i - NR;
            g_in[t] = __float2half_rn(inW[t]);
        } else if (i < NR + NI + NO) {
            int t = i - NR - NI;
            g_out[t] = __float2half_rn(outW[t]);
        }
    }
}

// ---------------- agg: relation scatter + x0 gather (fp16 hi outputs) ------
__global__ void __launch_bounds__(128)
agg_kernel(const int* __restrict__ drug,
           const int* __restrict__ adjE,
           const int* __restrict__ adjR,
           const float* __restrict__ ew,
           const float* __restrict__ E)
{
    __shared__ float s[NREL * DIM];
    __shared__ int   se[KNBR];
    __shared__ int   sr[KNBR];
    __shared__ float sw[KNBR];

    const int b = blockIdx.x;
    const int d = threadIdx.x;

    #pragma unroll
    for (int r = 0; r < NREL; r++) s[r * DIM + d] = 0.f;

    if (d < KNBR) {
        se[d] = adjE[b * KNBR + d];
        sr[d] = adjR[b * KNBR + d];
        sw[d] = ew  [b * KNBR + d];
    }
    {
        float v = E[(long)drug[b] * DIM + d];
        g_x[0][b * DIM + d] = v;
        g_xh[b * DIM + d] = __float2half_rn(v);
    }
    __syncthreads();

    #pragma unroll 1
    for (int k = 0; k < KNBR; k += 4) {
        float e0 = E[(long)se[k + 0] * DIM + d];
        float e1 = E[(long)se[k + 1] * DIM + d];
        float e2 = E[(long)se[k + 2] * DIM + d];
        float e3 = E[(long)se[k + 3] * DIM + d];
        s[sr[k + 0] * DIM + d] += sw[k + 0] * e0;
        s[sr[k + 1] * DIM + d] += sw[k + 1] * e1;
        s[sr[k + 2] * DIM + d] += sw[k + 2] * e2;
        s[sr[k + 3] * DIM + d] += sw[k + 3] * e3;
    }
    const long ao = (long)b * KAGG;
    #pragma unroll
    for (int r = 0; r < NREL; r++)
        g_aggh[ao + r * DIM + d] = __float2half_rn(s[r * DIM + d]);
}

// ================= fp16 tensor-core GEMM, 32-wide k-tiles ==================
// 256 threads / 8 warps; CTA tile 128x128; warp tile 32x64; 2 CTAs/SM.
// C[m,n] = sum_k A[m,k]*B[n,k]; A = [A1 | A2] fp16 (lo limbs iff NPASS==2).
// 3-stage cp.async pipeline, ONE barrier per k-tile.
// HALF_OUT: write __half C (split-K partials); else float C (+bias).
#define ROWB   80
#define REGB   10240            // 128 * 80

template<int NPASS, bool HALF_OUT>
__global__ void __launch_bounds__(256, 2)
gemm_f16(const __half* __restrict__ A1h, const __half* __restrict__ A1l, int K1,
         const __half* __restrict__ A2h, const __half* __restrict__ A2l, int K2,
         const __half* __restrict__ Bm, int KB,
         void* __restrict__ Cv, int ldC, long partStride,
         int tiles_total, const float* __restrict__ bias)
{
    constexpr u32 STAGE = (NPASS + 1) * REGB;
    constexpr u32 BOFF  = NPASS * REGB;

    extern __shared__ __align__(128) char smem[];
    const u32 sb  = smem_u32(smem);
    const int tid = threadIdx.x, lane = tid & 31, wid = tid >> 5;
    const int bm  = blockIdx.x * 128;
    const int bn  = blockIdx.y * 128;

    const int tb = (tiles_total * blockIdx.z) / gridDim.z;
    const int te = (tiles_total * (blockIdx.z + 1)) / gridDim.z;
    const int ntiles = te - tb;
    const int kbeg = tb * 32;

    // producer mapping: thread -> (row, 16-elem segment)
    const int prow = tid >> 1, pseg = tid & 1;
    const u32 pdst = (u32)(prow * ROWB + pseg * 32);

    auto issue = [&](int t, int s) {
        const int k0 = kbeg + t * 32;
        const __half *pAh, *pAl = nullptr;
        if (k0 < K1) {
            long o = (long)(bm + prow) * K1 + k0 + pseg * 16;
            pAh = A1h + o; if (NPASS == 2) pAl = A1l + o;
        } else {
            long o = (long)(bm + prow) * K2 + (k0 - K1) + pseg * 16;
            pAh = A2h + o; if (NPASS == 2) pAl = A2l + o;
        }
        long ob = (long)(bn + prow) * KB + k0 + pseg * 16;
        u32 d = sb + s * STAGE + pdst;
        cp16(d,        pAh);      cp16(d + 16,        pAh + 8);
        if (NPASS == 2) {
            cp16(d + REGB, pAl);  cp16(d + REGB + 16, pAl + 8);
        }
        cp16(d + BOFF, Bm + ob);  cp16(d + BOFF + 16, Bm + ob + 8);
        cp_commit();
    };

    // consumer mapping: 8 warps -> 4 (m) x 2 (n); warp tile 32x64
    const int wr = wid & 3, wc = wid >> 2;
    const u32 a_off = (u32)((wr * 32 + (lane & 15)) * ROWB + (lane >> 4) * 16);
    const u32 b_off = (u32)(BOFF +
                            (wc * 64 + (lane & 7) + ((lane >> 4) & 1) * 8) * ROWB +
                            ((lane >> 3) & 1) * 16);

    float acc[2][8][4];
    #pragma unroll
    for (int i = 0; i < 2; i++)
        #pragma unroll
        for (int j = 0; j < 8; j++)
            #pragma unroll
            for (int q = 0; q < 4; q++) acc[i][j][q] = 0.f;

    issue(0, 0);
    if (ntiles > 1) issue(1, 1);

    for (int t = 0; t < ntiles; t++) {
        const int s = t % 3;
        if (t + 1 < ntiles) cp_wait1(); else cp_wait0();
        __syncthreads();   // stage s visible; all warps done with stage (t+2)%3
        if (t + 2 < ntiles) issue(t + 2, (t + 2) % 3);

        const u32 base = sb + s * STAGE;
        #pragma unroll
        for (int kk = 0; kk < 32; kk += 16) {
            u32 ah[2][4], bx[4][4];
            #pragma unroll
            for (int mi = 0; mi < 2; mi++)
                ldsm4(ah[mi], base + a_off + mi * (16 * ROWB) + kk * 2);
            #pragma unroll
            for (int nj = 0; nj < 4; nj++)
                ldsm4(bx[nj], base + b_off + nj * (16 * ROWB) + kk * 2);
            #pragma unroll
            for (int mi = 0; mi < 2; mi++)
                #pragma unroll
                for (int nt = 0; nt < 8; nt++)
                    mma16816(acc[mi][nt], ah[mi], &bx[nt >> 1][(nt & 1) * 2]);
            if (NPASS == 2) {
                u32 al[2][4];
                #pragma unroll
                for (int mi = 0; mi < 2; mi++)
                    ldsm4(al[mi], base + REGB + a_off + mi * (16 * ROWB) + kk * 2);
                #pragma unroll
                for (int mi = 0; mi < 2; mi++)
                    #pragma unroll
                    for (int nt = 0; nt < 8; nt++)
                        mma16816(acc[mi][nt], al[mi], &bx[nt >> 1][(nt & 1) * 2]);
            }
        }
    }

    // epilogue
    const int gr  = bm + wr * 32 + (lane >> 2);
    const int gcb = bn + wc * 64 + (lane & 3) * 2;
    if (HALF_OUT) {
        __half* Cp = (__half*)Cv + (long)blockIdx.z * partStride;
        #pragma unroll
        for (int mi = 0; mi < 2; mi++)
            #pragma unroll
            for (int nt = 0; nt < 8; nt++) {
                int r0 = gr + mi * 16;
                int c  = gcb + nt * 8;
                *(__half2*)(Cp + (long)r0 * ldC + c) =
                    __halves2half2(__float2half_rn(acc[mi][nt][0]), __float2half_rn(acc[mi][nt][1]));
                *(__half2*)(Cp + (long)(r0 + 8) * ldC + c) =
                    __halves2half2(__float2half_rn(acc[mi][nt][2]), __float2half_rn(acc[mi][nt][3]));
            }
    } else {
        float* Cp = (float*)Cv + (long)blockIdx.z * partStride;
        #pragma unroll
        for (int mi = 0; mi < 2; mi++)
            #pragma unroll
            for (int nt = 0; nt < 8; nt++) {
                int r0 = gr + mi * 16;
                int c  = gcb + nt * 8;
                float b0 = 0.f, b1 = 0.f;
                if (bias) { b0 = bias[c]; b1 = bias[c + 1]; }
                *(float2*)(Cp + (long)r0 * ldC + c) =
                    make_float2(acc[mi][nt][0] + b0, acc[mi][nt][1] + b1);
                *(float2*)(Cp + (long)(r0 + 8) * ldC + c) =
                    make_float2(acc[mi][nt][2] + b0, acc[mi][nt][3] + b1);
            }
    }
}

// ---------------- split-K combine (fp16 partials) + bias + residual + relu -
__global__ void __launch_bounds__(256)
combine_layer(const float* __restrict__ bias,
              const float* __restrict__ xin,
              float* __restrict__ xout,
              __half* __restrict__ xh)
{
    const int i = blockIdx.x * 256 + threadIdx.x;      // over BSZ*DIM/4
    const __half2* p = (const __half2*)g_part;
    const int Q2 = BSZ * DIM / 2;
    float2 a01 = make_float2(0.f, 0.f), a23 = make_float2(0.f, 0.f);
    #pragma unroll
    for (int q = 0; q < NSPLIT; q++) {
        float2 v0 = __half22float2(p[q * Q2 + 2 * i]);
        float2 v1 = __half22float2(p[q * Q2 + 2 * i + 1]);
        a01.x += v0.x; a01.y += v0.y; a23.x += v1.x; a23.y += v1.y;
    }
    float4 xi = ((const float4*)xin)[i];
    float4 bb = ((const float4*)bias)[i & 31];
    float4 o;
    o.x = fmaxf(a01.x + xi.x + bb.x, 0.f);
    o.y = fmaxf(a01.y + xi.y + bb.y, 0.f);
    o.z = fmaxf(a23.x + xi.z + bb.z, 0.f);
    o.w = fmaxf(a23.y + xi.w + bb.w, 0.f);
    ((float4*)xout)[i] = o;

    __half2* ph = (__half2*)xh;
    ph[2 * i]     = __halves2half2(__float2half_rn(o.x), __float2half_rn(o.y));
    ph[2 * i + 1] = __halves2half2(__float2half_rn(o.z), __float2half_rn(o.w));
}

// ---------------- attention (L=2, one warp per head) ----------------
__global__ void __launch_bounds__(128)
attn_kernel()
{
    const int b = blockIdx.x;
    const int h = threadIdx.x >> 5;
    const int d = threadIdx.x & 31;

    const float* p0 = g_qkv + (long)b * NQKV + h * 32 + d;
    const float* p1 = p0 + (long)BSZ * NQKV;
    float q0 = p0[0], k0 = p0[128], v0 = p0[256];
    float q1 = p1[0], k1 = p1[128], v1 = p1[256];

    float s00 = q0 * k0, s01 = q0 * k1, s10 = q1 * k0, s11 = q1 * k1;
    #pragma unroll
    for (int o = 16; o; o >>= 1) {
        s00 += __shfl_xor_sync(0xffffffffu, s00, o);
        s01 += __shfl_xor_sync(0xffffffffu, s01, o);
        s10 += __shfl_xor_sync(0xffffffffu, s10, o);
        s11 += __shfl_xor_sync(0xffffffffu, s11, o);
    }
    const float inv = 0.17677669529663687f;  // 1/sqrt(32)
    s00 *= inv; s01 *= inv; s10 *= inv; s11 *= inv;

    float m0 = fmaxf(s00, s01), m1 = fmaxf(s10, s11);
    float e00 = expf(s00 - m0), e01 = expf(s01 - m0);
    float e10 = expf(s10 - m1), e11 = expf(s11 - m1);
    float o0 = (e00 * v0 + e01 * v1) / (e00 + e01);
    float o1 = (e10 * v0 + e11 * v1) / (e10 + e11);

    float v = 0.5f * (o0 + o1);
    __half hh, ll; split_f16(v, hh, ll);
    g_oh[(long)b * DIM + h * 32 + d] = hh;
    g_ol[(long)b * DIM + h * 32 + d] = ll;
}

// ---------------- host launcher ----------------
extern "C" void kernel_launch(void* const* d_in, const int* in_sizes, int n_in,
                              void* d_out, int out_size)
{
    const int*   drug = (const int*)  d_in[0];
    const int*   adjE = (const int*)  d_in[1];
    const int*   adjR = (const int*)  d_in[2];
    const float* ew   = (const float*)d_in[3];
    const float* E    = (const float*)d_in[4];
    const float* Wrel = (const float*)d_in[5];
    const float* resW = (const float*)d_in[6];
    const float* resb = (const float*)d_in[7];
    const float* inW  = (const float*)d_in[8];
    const float* inB  = (const float*)d_in[9];
    const float* outW = (const float*)d_in[10];
    const float* outB = (const float*)d_in[11];

    __half *aggh, *xh, *oh, *ol, *Wt, *inw, *outw, *part;
    float *xf, *qkv;
    cudaGetSymbolAddress((void**)&aggh, g_aggh);
    cudaGetSymbolAddress((void**)&xf,   g_x);
    cudaGetSymbolAddress((void**)&xh,   g_xh);
    cudaGetSymbolAddress((void**)&qkv,  g_qkv);
    cudaGetSymbolAddress((void**)&oh,   g_oh);
    cudaGetSymbolAddress((void**)&ol,   g_ol);
    cudaGetSymbolAddress((void**)&Wt,   g_Wt);
    cudaGetSymbolAddress((void**)&inw,  g_in);
    cudaGetSymbolAddress((void**)&outw, g_out);
    cudaGetSymbolAddress((void**)&part, g_part);

    const int SM1 = 3 * 2 * REGB;   // 61440
    const int SM2 = 3 * 3 * REGB;   // 92160
    cudaFuncSetAttribute((const void*)gemm_f16<1, true>,
                         cudaFuncAttributeMaxDynamicSharedMemorySize, SM1);
    cudaFuncSetAttribute((const void*)gemm_f16<1, false>,
                         cudaFuncAttributeMaxDynamicSharedMemorySize, SM1);
    cudaFuncSetAttribute((const void*)gemm_f16<2, false>,
                         cudaFuncAttributeMaxDynamicSharedMemorySize, SM2);

    prep_all<<<896, 256>>>(Wrel, resW, inW, outW);
    agg_kernel<<<BSZ, 128>>>(drug, adjE, adjR, ew, E);

    // layer 0 (1-pass, fp16 partials): part = split-K((agg|x0) @ Wcat0^T)
    gemm_f16<1, true><<<dim3(BSZ / 128, 1, NSPLIT), 256, SM1>>>(
        aggh, nullptr, KAGG, xh, nullptr, DIM, Wt, KCAT,
        part, DIM, (long)BSZ * DIM, LAYER_TILES, nullptr);
    combine_layer<<<BSZ * DIM / 4 / 256, 256>>>(
        resb, xf, xf + BSZ * DIM, xh + BSZ * DIM);

    // layer 1 (1-pass, fp16 partials)
    gemm_f16<1, true><<<dim3(BSZ / 128, 1, NSPLIT), 256, SM1>>>(
        aggh, nullptr, KAGG, xh + BSZ * DIM, nullptr, DIM,
        Wt + DIM * KCAT, KCAT,
        part, DIM, (long)BSZ * DIM, LAYER_TILES, nullptr);
    combine_layer<<<BSZ * DIM / 4 / 256, 256>>>(
        resb + DIM, xf + BSZ * DIM, xf + 2 * BSZ * DIM,
        xh + 2 * BSZ * DIM);

    // qkv for both layer outputs (1-pass, fp32 out): M=8192, N=384, K=128
    gemm_f16<1, false><<<dim3(2 * BSZ / 128, NQKV / 128, 1), 256, SM1>>>(
        xh + BSZ * DIM, nullptr, DIM, nullptr, nullptr, 0,
        inw, DIM, qkv, NQKV, 0, 4, inB);

    attn_kernel<<<BSZ, 128>>>();

    // out projection (2-pass, fp32 out): M=4096, N=128, K=128 -> d_out
    gemm_f16<2, false><<<dim3(BSZ / 128, 1, 1), 256, SM2>>>(
        oh, ol, DIM, nullptr, nullptr, 0,
        outw, DIM, d_out, DIM, 0, 4, outB);
}

// round 15
// speedup vs baseline: 1.0928x; 1.0251x over previous
#include <cuda_runtime.h>
#include <cuda_fp16.h>
#include <math.h>
#include <stdint.h>

typedef unsigned long long u64;
typedef unsigned int u32;

// ---------------- problem constants ----------------
#define BSZ   4096
#define DIM   128
#define KNBR  64
#define NREL  16
#define KAGG  2048          // NREL * DIM
#define KCAT  2176          // KAGG + DIM
#define NQKV  384
#define NSPLIT 8            // split-K for layer GEMMs (68 tiles -> 8..9 each)
#define LAYER_TILES 68      // KCAT / 32

// ---------------- device scratch ----------------
__device__ __half g_aggh[BSZ * KAGG];
__device__ float  g_x   [3][BSZ * DIM];        // fp32 x0,x1 (residuals)
__device__ __half g_xh  [3 * BSZ * DIM];       // x0,x1,x2 hi
__device__ __half g_qkvh[2 * BSZ * NQKV];      // fp16 qkv
__device__ __half g_oh  [BSZ * DIM];
__device__ __half g_ol  [BSZ * DIM];
__device__ __half g_Wt  [2 * DIM * KCAT];      // B for layer gemm, [l][e][k], fp16
__device__ __half g_in  [NQKV * DIM];          // in_proj_w fp16
__device__ __half g_out [DIM * DIM];           // out_proj_w fp16
__device__ __half g_part[NSPLIT * BSZ * DIM];  // fp16 split-K partials

// ================= PTX helpers =================
__device__ __forceinline__ u32 smem_u32(const void* p) {
    u32 a; asm("{ .reg .u64 t; cvta.to.shared.u64 t, %1; cvt.u32.u64 %0, t; }" : "=r"(a) : "l"(p));
    return a;
}
__device__ __forceinline__ void cp16(u32 s, const void* g) {
    asm volatile("cp.async.cg.shared.global [%0], [%1], 16;" :: "r"(s), "l"(g));
}
__device__ __forceinline__ void cp_commit() {
    asm volatile("cp.async.commit_group;" ::: "memory");
}
__device__ __forceinline__ void cp_wait0() {
    asm volatile("cp.async.wait_group 0;" ::: "memory");
}
__device__ __forceinline__ void cp_wait1() {
    asm volatile("cp.async.wait_group 1;" ::: "memory");
}
__device__ __forceinline__ void ldsm4(u32* r, u32 addr) {
    asm volatile("ldmatrix.sync.aligned.m8n8.x4.shared.b16 {%0,%1,%2,%3}, [%4];"
                 : "=r"(r[0]), "=r"(r[1]), "=r"(r[2]), "=r"(r[3]) : "r"(addr));
}
__device__ __forceinline__ void mma16816(float* c, const u32* a, const u32* b) {
    asm volatile(
        "mma.sync.aligned.m16n8k16.row.col.f32.f16.f16.f32 "
        "{%0,%1,%2,%3}, {%4,%5,%6,%7}, {%8,%9}, {%0,%1,%2,%3};"
        : "+f"(c[0]), "+f"(c[1]), "+f"(c[2]), "+f"(c[3])
        : "r"(a[0]), "r"(a[1]), "r"(a[2]), "r"(a[3]), "r"(b[0]), "r"(b[1]));
}
__device__ __forceinline__ void split_f16(float v, __half& h, __half& l) {
    h = __float2half_rn(v);
    l = __float2half_rn(v - __half2float(h));
}

// ================= merged prep + agg kernel =================
// blocks [0,512): transpose W_rel -> g_Wt
// blocks [512,896): res_W copy + inW/outW fp16 conversion
// blocks [896, 896+2048): agg scatter, 2 batch-rows per block
__global__ void __launch_bounds__(256)
prep_agg(const float* __restrict__ Wrel,
         const float* __restrict__ resW,
         const float* __restrict__ inW,
         const float* __restrict__ outW,
         const int* __restrict__ drug,
         const int* __restrict__ adjE,
         const int* __restrict__ adjR,
         const float* __restrict__ ew,
         const float* __restrict__ E)
{
    const int blk = blockIdx.x;
    if (blk < 512) {
        __shared__ float tile[32][33];
        const int mat = blk >> 4;            // l*16 + r
        const int by  = (blk >> 2) & 3;
        const int bx  = blk & 3;
        const int l = mat >> 4, r = mat & 15;
        const int tx = threadIdx.x & 31, ty = threadIdx.x >> 5;
        const float* src = Wrel + (long)mat * 16384;
        int e_in = bx * 32 + tx;
        #pragma unroll
        for (int i = 0; i < 4; i++) {
            int d = by * 32 + ty + i * 8;
            tile[ty + i * 8][tx] = src[d * 128 + e_in];
        }
        __syncthreads();
        const long base = (long)l * (DIM * KCAT);
        #pragma unroll
        for (int i = 0; i < 4; i++) {
            int e = bx * 32 + ty + i * 8;
            int d = by * 32 + tx;
            g_Wt[base + (long)e * KCAT + r * 128 + d] = __float2half_rn(tile[tx][ty + i * 8]);
        }
    } else if (blk < 896) {
        int i = (blk - 512) * 256 + threadIdx.x;
        const int NR = 2 * DIM * DIM;
        const int NI = NQKV * DIM;
        const int NO = DIM * DIM;
        if (i < NR) {
            int l = i >> 14, e = (i >> 7) & 127, d = i & 127;
            g_Wt[(long)l * (DIM * KCAT) + (long)e * KCAT + 2048 + d] = __float2half_rn(resW[i]);
        } else if (i < NR + NI) {
            int t = i - NR;
            g_in[t] = __float2half_rn(inW[t]);
        } else if (i < NR + NI + NO) {
            int t = i - NR - NI;
            g_out[t] = __float2half_rn(outW[t]);
        }
    } else {
        // agg: two batch rows per block
        __shared__ float s[2][NREL * DIM];
        __shared__ int   se[2][KNBR];
        __shared__ int   sr[2][KNBR];
        __shared__ float sw[2][KNBR];

        const int half_id = threadIdx.x >> 7;
        const int d = threadIdx.x & 127;
        const int b = (blk - 896) * 2 + half_id;
        float* sp = s[half_id];

        #pragma unroll
        for (int r = 0; r < NREL; r++) sp[r * DIM + d] = 0.f;

        if (d < KNBR) {
            se[half_id][d] = adjE[b * KNBR + d];
            sr[half_id][d] = adjR[b * KNBR + d];
            sw[half_id][d] = ew  [b * KNBR + d];
        }
        {
            float v = E[(long)drug[b] * DIM + d];
            g_x[0][b * DIM + d] = v;
            g_xh[b * DIM + d] = __float2half_rn(v);
        }
        __syncthreads();

        #pragma unroll 1
        for (int k = 0; k < KNBR; k += 4) {
            float e0 = E[(long)se[half_id][k + 0] * DIM + d];
            float e1 = E[(long)se[half_id][k + 1] * DIM + d];
            float e2 = E[(long)se[half_id][k + 2] * DIM + d];
            float e3 = E[(long)se[half_id][k + 3] * DIM + d];
            sp[sr[half_id][k + 0] * DIM + d] += sw[half_id][k + 0] * e0;
            sp[sr[half_id][k + 1] * DIM + d] += sw[half_id][k + 1] * e1;
            sp[sr[half_id][k + 2] * DIM + d] += sw[half_id][k + 2] * e2;
            sp[sr[half_id][k + 3] * DIM + d] += sw[half_id][k + 3] * e3;
        }
        const long ao = (long)b * KAGG;
        #pragma unroll
        for (int r = 0; r < NREL; r++)
            g_aggh[ao + r * DIM + d] = __float2half_rn(sp[r * DIM + d]);
    }
}

// ================= fp16 tensor-core GEMM, 32-wide k-tiles ==================
// 256 threads / 8 warps; CTA tile 128x128; warp tile 32x64; 2 CTAs/SM.
// C[m,n] = sum_k A[m,k]*B[n,k]; A = [A1 | A2] fp16 (lo limbs iff NPASS==2).
// 3-stage cp.async pipeline, ONE barrier per k-tile.
// HALF_OUT: write __half C; else float C. bias applied in both paths.
#define ROWB   80
#define REGB   10240            // 128 * 80

template<int NPASS, bool HALF_OUT>
__global__ void __launch_bounds__(256, 2)
gemm_f16(const __half* __restrict__ A1h, const __half* __restrict__ A1l, int K1,
         const __half* __restrict__ A2h, const __half* __restrict__ A2l, int K2,
         const __half* __restrict__ Bm, int KB,
         void* __restrict__ Cv, int ldC, long partStride,
         int tiles_total, const float* __restrict__ bias)
{
    constexpr u32 STAGE = (NPASS + 1) * REGB;
    constexpr u32 BOFF  = NPASS * REGB;

    extern __shared__ __align__(128) char smem[];
    const u32 sb  = smem_u32(smem);
    const int tid = threadIdx.x, lane = tid & 31, wid = tid >> 5;
    const int bm  = blockIdx.x * 128;
    const int bn  = blockIdx.y * 128;

    const int tb = (tiles_total * blockIdx.z) / gridDim.z;
    const int te = (tiles_total * (blockIdx.z + 1)) / gridDim.z;
    const int ntiles = te - tb;
    const int kbeg = tb * 32;

    // producer mapping: thread -> (row, 16-elem segment)
    const int prow = tid >> 1, pseg = tid & 1;
    const u32 pdst = (u32)(prow * ROWB + pseg * 32);

    auto issue = [&](int t, int s) {
        const int k0 = kbeg + t * 32;
        const __half *pAh, *pAl = nullptr;
        if (k0 < K1) {
            long o = (long)(bm + prow) * K1 + k0 + pseg * 16;
            pAh = A1h + o; if (NPASS == 2) pAl = A1l + o;
        } else {
            long o = (long)(bm + prow) * K2 + (k0 - K1) + pseg * 16;
            pAh = A2h + o; if (NPASS == 2) pAl = A2l + o;
        }
        long ob = (long)(bn + prow) * KB + k0 + pseg * 16;
        u32 d = sb + s * STAGE + pdst;
        cp16(d,        pAh);      cp16(d + 16,        pAh + 8);
        if (NPASS == 2) {
            cp16(d + REGB, pAl);  cp16(d + REGB + 16, pAl + 8);
        }
        cp16(d + BOFF, Bm + ob);  cp16(d + BOFF + 16, Bm + ob + 8);
        cp_commit();
    };

    // consumer mapping: 8 warps -> 4 (m) x 2 (n); warp tile 32x64
    const int wr = wid & 3, wc = wid >> 2;
    const u32 a_off = (u32)((wr * 32 + (lane & 15)) * ROWB + (lane >> 4) * 16);
    const u32 b_off = (u32)(BOFF +
                            (wc * 64 + (lane & 7) + ((lane >> 4) & 1) * 8) * ROWB +
                            ((lane >> 3) & 1) * 16);

    float acc[2][8][4];
    #pragma unroll
    for (int i = 0; i < 2; i++)
        #pragma unroll
        for (int j = 0; j < 8; j++)
            #pragma unroll
            for (int q = 0; q < 4; q++) acc[i][j][q] = 0.f;

    issue(0, 0);
    if (ntiles > 1) issue(1, 1);

    for (int t = 0; t < ntiles; t++) {
        const int s = t % 3;
        if (t + 1 < ntiles) cp_wait1(); else cp_wait0();
        __syncthreads();   // stage s visible; all warps done with stage (t+2)%3
        if (t + 2 < ntiles) issue(t + 2, (t + 2) % 3);

        const u32 base = sb + s * STAGE;
        #pragma unroll
        for (int kk = 0; kk < 32; kk += 16) {
            u32 ah[2][4], bx[4][4];
            #pragma unroll
            for (int mi = 0; mi < 2; mi++)
                ldsm4(ah[mi], base + a_off + mi * (16 * ROWB) + kk * 2);
            #pragma unroll
            for (int nj = 0; nj < 4; nj++)
                ldsm4(bx[nj], base + b_off + nj * (16 * ROWB) + kk * 2);
            #pragma unroll
            for (int mi = 0; mi < 2; mi++)
                #pragma unroll
                for (int nt = 0; nt < 8; nt++)
                    mma16816(acc[mi][nt], ah[mi], &bx[nt >> 1][(nt & 1) * 2]);
            if (NPASS == 2) {
                u32 al[2][4];
                #pragma unroll
                for (int mi = 0; mi < 2; mi++)
                    ldsm4(al[mi], base + REGB + a_off + mi * (16 * ROWB) + kk * 2);
                #pragma unroll
                for (int mi = 0; mi < 2; mi++)
                    #pragma unroll
                    for (int nt = 0; nt < 8; nt++)
                        mma16816(acc[mi][nt], al[mi], &bx[nt >> 1][(nt & 1) * 2]);
            }
        }
    }

    // epilogue
    const int gr  = bm + wr * 32 + (lane >> 2);
    const int gcb = bn + wc * 64 + (lane & 3) * 2;
    if (HALF_OUT) {
        __half* Cp = (__half*)Cv + (long)blockIdx.z * partStride;
        #pragma unroll
        for (int mi = 0; mi < 2; mi++)
            #pragma unroll
            for (int nt = 0; nt < 8; nt++) {
                int r0 = gr + mi * 16;
                int c  = gcb + nt * 8;
                float b0 = 0.f, b1 = 0.f;
                if (bias) { b0 = bias[c]; b1 = bias[c + 1]; }
                *(__half2*)(Cp + (long)r0 * ldC + c) =
                    __halves2half2(__float2half_rn(acc[mi][nt][0] + b0),
                                   __float2half_rn(acc[mi][nt][1] + b1));
                *(__half2*)(Cp + (long)(r0 + 8) * ldC + c) =
                    __halves2half2(__float2half_rn(acc[mi][nt][2] + b0),
                                   __float2half_rn(acc[mi][nt][3] + b1));
            }
    } else {
        float* Cp = (float*)Cv + (long)blockIdx.z * partStride;
        #pragma unroll
        for (int mi = 0; mi < 2; mi++)
            #pragma unroll
            for (int nt = 0; nt < 8; nt++) {
                int r0 = gr + mi * 16;
                int c  = gcb + nt * 8;
                float b0 = 0.f, b1 = 0.f;
                if (bias) { b0 = bias[c]; b1 = bias[c + 1]; }
                *(float2*)(Cp + (long)r0 * ldC + c) =
                    make_float2(acc[mi][nt][0] + b0, acc[mi][nt][1] + b1);
                *(float2*)(Cp + (long)(r0 + 8) * ldC + c) =
                    make_float2(acc[mi][nt][2] + b0, acc[mi][nt][3] + b1);
            }
    }
}

// ---------------- split-K combine (fp16 partials, 16B loads) ---------------
// 8 elements per thread; grid covers BSZ*DIM/8.
__global__ void __launch_bounds__(256)
combine_layer(const float* __restrict__ bias,
              const float* __restrict__ xin,
              float* __restrict__ xout,
              __half* __restrict__ xh)
{
    const int i = blockIdx.x * 256 + threadIdx.x;      // over BSZ*DIM/8
    const uint4* p = (const uint4*)g_part;
    const int Q = BSZ * DIM / 8;
    float a[8];
    #pragma unroll
    for (int e = 0; e < 8; e++) a[e] = 0.f;
    #pragma unroll
    for (int q = 0; q < NSPLIT; q++) {
        uint4 v = p[q * Q + i];
        float2 f0 = __half22float2(*(__half2*)&v.x);
        float2 f1 = __half22float2(*(__half2*)&v.y);
        float2 f2 = __half22float2(*(__half2*)&v.z);
        float2 f3 = __half22float2(*(__half2*)&v.w);
        a[0] += f0.x; a[1] += f0.y; a[2] += f1.x; a[3] += f1.y;
        a[4] += f2.x; a[5] += f2.y; a[6] += f3.x; a[7] += f3.y;
    }
    float4 xi0 = ((const float4*)xin)[2 * i];
    float4 xi1 = ((const float4*)xin)[2 * i + 1];
    float4 bb0 = ((const float4*)bias)[(2 * i) & 31];
    float4 bb1 = ((const float4*)bias)[(2 * i + 1) & 31];
    float o[8];
    o[0] = fmaxf(a[0] + xi0.x + bb0.x, 0.f);
    o[1] = fmaxf(a[1] + xi0.y + bb0.y, 0.f);
    o[2] = fmaxf(a[2] + xi0.z + bb0.z, 0.f);
    o[3] = fmaxf(a[3] + xi0.w + bb0.w, 0.f);
    o[4] = fmaxf(a[4] + xi1.x + bb1.x, 0.f);
    o[5] = fmaxf(a[5] + xi1.y + bb1.y, 0.f);
    o[6] = fmaxf(a[6] + xi1.z + bb1.z, 0.f);
    o[7] = fmaxf(a[7] + xi1.w + bb1.w, 0.f);
    ((float4*)xout)[2 * i]     = make_float4(o[0], o[1], o[2], o[3]);
    ((float4*)xout)[2 * i + 1] = make_float4(o[4], o[5], o[6], o[7]);

    uint4 hv;
    *(__half2*)&hv.x = __halves2half2(__float2half_rn(o[0]), __float2half_rn(o[1]));
    *(__half2*)&hv.y = __halves2half2(__float2half_rn(o[2]), __float2half_rn(o[3]));
    *(__half2*)&hv.z = __halves2half2(__float2half_rn(o[4]), __float2half_rn(o[5]));
    *(__half2*)&hv.w = __halves2half2(__float2half_rn(o[6]), __float2half_rn(o[7]));
    ((uint4*)xh)[i] = hv;
}

// ---------------- attention (L=2, one warp per head, fp16 qkv) -------------
__global__ void __launch_bounds__(128)
attn_kernel()
{
    const int b = blockIdx.x;
    const int h = threadIdx.x >> 5;
    const int d = threadIdx.x & 31;

    const __half* p0 = g_qkvh + (long)b * NQKV + h * 32 + d;
    const __half* p1 = p0 + (long)BSZ * NQKV;
    float q0 = __half2float(p0[0]), k0 = __half2float(p0[128]), v0 = __half2float(p0[256]);
    float q1 = __half2float(p1[0]), k1 = __half2float(p1[128]), v1 = __half2float(p1[256]);

    float s00 = q0 * k0, s01 = q0 * k1, s10 = q1 * k0, s11 = q1 * k1;
    #pragma unroll
    for (int o = 16; o; o >>= 1) {
        s00 += __shfl_xor_sync(0xffffffffu, s00, o);
        s01 += __shfl_xor_sync(0xffffffffu, s01, o);
        s10 += __shfl_xor_sync(0xffffffffu, s10, o);
        s11 += __shfl_xor_sync(0xffffffffu, s11, o);
    }
    const float inv = 0.17677669529663687f;  // 1/sqrt(32)
    s00 *= inv; s01 *= inv; s10 *= inv; s11 *= inv;

    float m0 = fmaxf(s00, s01), m1 = fmaxf(s10, s11);
    float e00 = expf(s00 - m0), e01 = expf(s01 - m0);
    float e10 = expf(s10 - m1), e11 = expf(s11 - m1);
    float o0 = (e00 * v0 + e01 * v1) / (e00 + e01);
    float o1 = (e10 * v0 + e11 * v1) / (e10 + e11);

    float v = 0.5f * (o0 + o1);
    __half hh, ll; split_f16(v, hh, ll);
    g_oh[(long)b * DIM + h * 32 + d] = hh;
    g_ol[(long)b * DIM + h * 32 + d] = ll;
}

// ---------------- host launcher ----------------
extern "C" void kernel_launch(void* const* d_in, const int* in_sizes, int n_in,
                              void* d_out, int out_size)
{
    const int*   drug = (const int*)  d_in[0];
    const int*   adjE = (const int*)  d_in[1];
    const int*   adjR = (const int*)  d_in[2];
    const float* ew   = (const float*)d_in[3];
    const float* E    = (const float*)d_in[4];
    const float* Wrel = (const float*)d_in[5];
    const float* resW = (const float*)d_in[6];
    const float* resb = (const float*)d_in[7];
    const float* inW  = (const float*)d_in[8];
    const float* inB  = (const float*)d_in[9];
    const float* outW = (const float*)d_in[10];
    const float* outB = (const float*)d_in[11];

    __half *aggh, *xh, *qkvh, *oh, *ol, *Wt, *inw, *outw, *part;
    float *xf;
    cudaGetSymbolAddress((void**)&aggh, g_aggh);
    cudaGetSymbolAddress((void**)&xf,   g_x);
    cudaGetSymbolAddress((void**)&xh,   g_xh);
    cudaGetSymbolAddress((void**)&qkvh, g_qkvh);
    cudaGetSymbolAddress((void**)&oh,   g_oh);
    cudaGetSymbolAddress((void**)&ol,   g_ol);
    cudaGetSymbolAddress((void**)&Wt,   g_Wt);
    cudaGetSymbolAddress((void**)&inw,  g_in);
    cudaGetSymbolAddress((void**)&outw, g_out);
    cudaGetSymbolAddress((void**)&part, g_part);

    const int SM1 = 3 * 2 * REGB;   // 61440
    const int SM2 = 3 * 3 * REGB;   // 92160
    cudaFuncSetAttribute((const void*)gemm_f16<1, true>,
                         cudaFuncAttributeMaxDynamicSharedMemorySize, SM1);
    cudaFuncSetAttribute((const void*)gemm_f16<2, false>,
                         cudaFuncAttributeMaxDynamicSharedMemorySize, SM2);

    prep_agg<<<896 + BSZ / 2, 256>>>(Wrel, resW, inW, outW, drug, adjE, adjR, ew, E);

    // layer 0 (1-pass, fp16 partials): part = split-K((agg|x0) @ Wcat0^T)
    gemm_f16<1, true><<<dim3(BSZ / 128, 1, NSPLIT), 256, SM1>>>(
        aggh, nullptr, KAGG, xh, nullptr, DIM, Wt, KCAT,
        part, DIM, (long)BSZ * DIM, LAYER_TILES, nullptr);
    combine_layer<<<BSZ * DIM / 8 / 256, 256>>>(
        resb, xf, xf + BSZ * DIM, xh + BSZ * DIM);

    // layer 1 (1-pass, fp16 partials)
    gemm_f16<1, true><<<dim3(BSZ / 128, 1, NSPLIT), 256, SM1>>>(
        aggh, nullptr, KAGG, xh + BSZ * DIM, nullptr, DIM,
        Wt + DIM * KCAT, KCAT,
        part, DIM, (long)BSZ * DIM, LAYER_TILES, nullptr);
    combine_layer<<<BSZ * DIM / 8 / 256, 256>>>(
        resb + DIM, xf + BSZ * DIM, xf + 2 * BSZ * DIM,
        xh + 2 * BSZ * DIM);

    // qkv (1-pass, fp16 out + bias): M=8192, N=384, K=128
    gemm_f16<1, true><<<dim3(2 * BSZ / 128, NQKV / 128, 1), 256, SM1>>>(
        xh + BSZ * DIM, nullptr, DIM, nullptr, nullptr, 0,
        inw, DIM, qkvh, NQKV, 0, 4, inB);

    attn_kernel<<<BSZ, 128>>>();

    // out projection (2-pass, fp32 out): M=4096, N=128, K=128 -> d_out
    gemm_f16<2, false><<<dim3(BSZ / 128, 1, 1), 256, SM2>>>(
        oh, ol, DIM, nullptr, nullptr, 0,
        outw, DIM, d_out, DIM, 0, 4, outB);
}